// round 5
// baseline (speedup 1.0000x reference)
#include <cuda_runtime.h>
#include <cuda_bf16.h>
#include <math.h>

#define NN 768
#define XD 768
#define HID 300
#define HP 304
#define W1COLS 1536
#define NJB 12            // j blocks in pair kernel (768/64)

typedef unsigned long long ull;

// Scratch (device globals -- no allocation allowed)
__device__ float g_hxT[HP * NN];   // [h][n] hx^T ("c" side), rows >=300 zeroed
__device__ float g_hyT[HP * NN];   // [h][n] hy^T
__device__ float g_aT[HP * NN];    // [h][i] a = hy[perm i][h] + b1[h], pad rows zero
__device__ float g_w2p[HP];        // w2, 0 for h>=HID
__device__ float g_Ai[NN];         // sum_h w*a_hi
__device__ float g_Cj[NN];         // sum_h w*c_hj
__device__ float g_t0[NN];
__device__ float g_pm[NJB][NN];    // per (jblock,row) partial max
__device__ float g_ps[NJB][NN];    // per (jblock,row) partial sum exp

__device__ __forceinline__ ull fma_f32x2(ull a, ull b, ull c) {
    ull d; asm("fma.rn.f32x2 %0, %1, %2, %3;" : "=l"(d) : "l"(a), "l"(b), "l"(c)); return d;
}
__device__ __forceinline__ ull dup_f32(float f) {
    ull d; unsigned u = __float_as_uint(f);
    asm("mov.b64 %0, {%1, %2};" : "=l"(d) : "r"(u), "r"(u)); return d;
}
__device__ __forceinline__ float lo_f(ull v) { return __uint_as_float((unsigned)(v & 0xffffffffu)); }
__device__ __forceinline__ float hi_f(ull v) { return __uint_as_float((unsigned)(v >> 32)); }
__device__ __forceinline__ float softplus_f(float z) {
    return fmaxf(z, 0.f) + log1pf(expf(-fabsf(z)));
}

// ---------------------------------------------------------------------------
// GEMM (packed f32x2): outT[h][n] = sum_k S[n][k]*W1[h][wofs+k]
// 64x64 tile, 16x16 threads; acc packed over n-pairs; W dup'ed in smem.
// ---------------------------------------------------------------------------
__global__ void gemm_hT(const float* __restrict__ x, const float* __restrict__ y,
                        const float* __restrict__ W1) {
    __shared__ float sS[32][68];   // [k][n]
    __shared__ ull   sWd[32][66];  // [k][h] dup'ed (pad 66 keeps 16B align)

    const int which = blockIdx.z;
    const float* S = which ? y : x;
    const int wofs = which ? XD : 0;
    float* outT = which ? g_hyT : g_hxT;

    const int n0 = blockIdx.x * 64;
    const int h0 = blockIdx.y * 64;
    const int tx = threadIdx.x, ty = threadIdx.y;
    const int tid = ty * 16 + tx;
    const int lr = tid >> 3;           // 0..31
    const int lc = (tid & 7) * 4;      // 0..28

    ull acc2[4][2] = {};               // [p(h)][q2(n-pair)]

    for (int k0 = 0; k0 < XD; k0 += 32) {
        {
            float4 v0 = *(const float4*)&S[(size_t)(n0 + lr) * XD + k0 + lc];
            float4 v1 = *(const float4*)&S[(size_t)(n0 + lr + 32) * XD + k0 + lc];
            sS[lc + 0][lr] = v0.x; sS[lc + 1][lr] = v0.y;
            sS[lc + 2][lr] = v0.z; sS[lc + 3][lr] = v0.w;
            sS[lc + 0][lr + 32] = v1.x; sS[lc + 1][lr + 32] = v1.y;
            sS[lc + 2][lr + 32] = v1.z; sS[lc + 3][lr + 32] = v1.w;
        }
        {
            const int h1 = h0 + lr, h2 = h0 + lr + 32;
            float4 v0 = make_float4(0.f, 0.f, 0.f, 0.f), v1 = v0;
            if (h1 < HID) v0 = *(const float4*)&W1[(size_t)h1 * W1COLS + wofs + k0 + lc];
            if (h2 < HID) v1 = *(const float4*)&W1[(size_t)h2 * W1COLS + wofs + k0 + lc];
            sWd[lc + 0][lr] = dup_f32(v0.x); sWd[lc + 1][lr] = dup_f32(v0.y);
            sWd[lc + 2][lr] = dup_f32(v0.z); sWd[lc + 3][lr] = dup_f32(v0.w);
            sWd[lc + 0][lr + 32] = dup_f32(v1.x); sWd[lc + 1][lr + 32] = dup_f32(v1.y);
            sWd[lc + 2][lr + 32] = dup_f32(v1.z); sWd[lc + 3][lr + 32] = dup_f32(v1.w);
        }
        __syncthreads();

        #pragma unroll
        for (int kk = 0; kk < 32; kk++) {
            ulonglong2 wa = *(const ulonglong2*)&sWd[kk][ty * 4];       // dup(h0..h1)
            ulonglong2 wb = *(const ulonglong2*)&sWd[kk][ty * 4 + 2];   // dup(h2..h3)
            ulonglong2 bp = *(const ulonglong2*)&sS[kk][tx * 4];        // {n0,n1},{n2,n3}
            ull wd[4] = {wa.x, wa.y, wb.x, wb.y};
            #pragma unroll
            for (int p = 0; p < 4; p++) {
                acc2[p][0] = fma_f32x2(wd[p], bp.x, acc2[p][0]);
                acc2[p][1] = fma_f32x2(wd[p], bp.y, acc2[p][1]);
            }
        }
        __syncthreads();
    }

    #pragma unroll
    for (int p = 0; p < 4; p++) {
        const int h = h0 + ty * 4 + p;
        if (h < HID) {
            float4 v = make_float4(lo_f(acc2[p][0]), hi_f(acc2[p][0]),
                                   lo_f(acc2[p][1]), hi_f(acc2[p][1]));
            *(float4*)&outT[(size_t)h * NN + n0 + tx * 4] = v;
        }
    }
}

// ---------------------------------------------------------------------------
// mid_kernel: blocks 0..227 -> aT build (float4) + pads; blocks 228..299 ->
// stats (mode 0: t0, 1: A_i, 2: C_j). 256 threads each.
// ---------------------------------------------------------------------------
__global__ void mid_kernel(const int* __restrict__ perm,
                           const float* __restrict__ b1,
                           const float* __restrict__ W2,
                           const float* __restrict__ b2) {
    __shared__ float red[8][33];
    const int b = blockIdx.x;
    const int t = threadIdx.x;

    if (b < 228) {   // 228*256*4 == HP*NN
        const int idx4 = b * 256 + t;
        const int h = idx4 / (NN / 4);
        const int i = (idx4 - h * (NN / 4)) * 4;
        float4 v = make_float4(0.f, 0.f, 0.f, 0.f);
        if (h < HID) {
            const int4 pi = *(const int4*)&perm[i];
            const float* row = &g_hyT[(size_t)h * NN];
            const float bh = b1[h];
            v.x = row[pi.x] + bh; v.y = row[pi.y] + bh;
            v.z = row[pi.z] + bh; v.w = row[pi.w] + bh;
        } else {
            *(float4*)&g_hxT[(size_t)h * NN + i] = v;   // zero pad c-side
        }
        *(float4*)&g_aT[(size_t)h * NN + i] = v;
        if (idx4 < HP) g_w2p[idx4] = (idx4 < HID) ? W2[idx4] : 0.f;
        return;
    }

    const int bs = b - 228;          // 0..71
    const int mode = bs / 24;
    const int tx = t & 31, ty = t >> 5;
    const int n = (bs % 24) * 32 + tx;

    float p = 0.f;
    if (mode == 0) {
        for (int h = ty; h < HID; h += 8) {
            float v = g_hxT[(size_t)h * NN + n] + g_hyT[(size_t)h * NN + n] + b1[h];
            p = fmaf(W2[h], fmaxf(v, 0.f), p);
        }
    } else if (mode == 1) {
        const int pi = perm[n];
        for (int h = ty; h < HID; h += 8)
            p = fmaf(W2[h], g_hyT[(size_t)h * NN + pi] + b1[h], p);
    } else {
        for (int h = ty; h < HID; h += 8)
            p = fmaf(W2[h], g_hxT[(size_t)h * NN + n], p);
    }
    red[ty][tx] = p;
    __syncthreads();
    if (ty == 0) {
        float s = red[0][tx];
        #pragma unroll
        for (int k = 1; k < 8; k++) s += red[k][tx];
        if (mode == 0)      g_t0[n] = softplus_f(s + b2[0]);
        else if (mode == 1) g_Ai[n] = s;
        else                g_Cj[n] = s;
    }
}

// ---------------------------------------------------------------------------
// Pair v4: 512 thr, 2-way h-split; scalar 4x4 micro-tile with fabs folded
// into FFMA. Epilogue computes softplus and per-(row, jblock) LSE partials
// (max & sumexp) via shfl in 16-lane groups -- no t1 matrix.
// ---------------------------------------------------------------------------
__global__ void __launch_bounds__(512, 1) pair_kernel(const float* __restrict__ b2) {
    __shared__ float sA[2][16][64];
    __shared__ float sC[2][16][64];
    __shared__ float sw[2][16];
    __shared__ float cbuf[256][16];

    const int g  = threadIdx.y;        // 0 or 1
    const int t  = threadIdx.x;        // 0..255
    const int tx = t & 15;             // j quad
    const int ty = t >> 4;             // i quad
    const int i0 = blockIdx.y * 64;
    const int j0 = blockIdx.x * 64;
    const int lr = t >> 4;
    const int lc = (t & 15) * 4;

    const int c0 = g ? 10 : 0;
    const int c1 = g ? 19 : 10;        // 19 chunks (HP=304)

    float acc[4][4] = {};

    for (int ch = c0; ch < c1; ch++) {
        const int h0 = ch * 16;
        *(float4*)&sA[g][lr][lc] = *(const float4*)&g_aT[(size_t)(h0 + lr) * NN + i0 + lc];
        *(float4*)&sC[g][lr][lc] = *(const float4*)&g_hxT[(size_t)(h0 + lr) * NN + j0 + lc];
        if (t < 16) sw[g][t] = g_w2p[h0 + t];
        asm volatile("bar.sync %0, 256;" :: "r"(g + 1) : "memory");

        #pragma unroll
        for (int hh = 0; hh < 16; hh++) {
            const float w = sw[g][hh];
            float4 a4 = *(const float4*)&sA[g][hh][ty * 4];
            float4 c4 = *(const float4*)&sC[g][hh][tx * 4];
            float a[4] = {a4.x, a4.y, a4.z, a4.w};
            float c[4] = {c4.x, c4.y, c4.z, c4.w};
            #pragma unroll
            for (int p = 0; p < 4; p++)
                #pragma unroll
                for (int q = 0; q < 4; q++)
                    acc[p][q] = fmaf(w, fabsf(a[p] + c[q]), acc[p][q]);
        }
        asm volatile("bar.sync %0, 256;" :: "r"(g + 1) : "memory");
    }

    // combine subgroup partials
    if (g == 1) {
        #pragma unroll
        for (int p = 0; p < 4; p++)
            *(float4*)&cbuf[t][p * 4] = *(float4*)&acc[p][0];
    }
    __syncthreads();
    if (g == 0) {
        const float bb = b2[0];
        float cj[4], ai[4];
        *(float4*)cj = *(const float4*)&g_Cj[j0 + tx * 4];
        *(float4*)ai = *(const float4*)&g_Ai[i0 + ty * 4];

        #pragma unroll
        for (int p = 0; p < 4; p++) {
            float v[4];
            #pragma unroll
            for (int q = 0; q < 4; q++) {
                float s = acc[p][q] + cbuf[t][p * 4 + q];
                v[q] = softplus_f(fmaf(0.5f, s + ai[p] + cj[q], bb));
            }
            // per-row LSE partial over this 64-j block (16 lanes share row)
            float m = fmaxf(fmaxf(v[0], v[1]), fmaxf(v[2], v[3]));
            #pragma unroll
            for (int o = 1; o < 16; o <<= 1)
                m = fmaxf(m, __shfl_xor_sync(0xffffffffu, m, o));
            float s = expf(v[0] - m) + expf(v[1] - m) + expf(v[2] - m) + expf(v[3] - m);
            #pragma unroll
            for (int o = 1; o < 16; o <<= 1)
                s += __shfl_xor_sync(0xffffffffu, s, o);
            if (tx == 0) {
                g_pm[blockIdx.x][i0 + ty * 4 + p] = m;
                g_ps[blockIdx.x][i0 + ty * 4 + p] = s;
            }
        }
    }
}

// ---------------------------------------------------------------------------
// Merge partials -> row LSE -> final scalar. One CTA, deterministic.
// ---------------------------------------------------------------------------
__global__ void final_kernel(float* __restrict__ out) {
    __shared__ float r0[256], r1[256];
    const int t = threadIdx.x;
    float s0 = 0.f, s1 = 0.f;
    for (int r = t; r < NN; r += 256) {
        float m = -INFINITY;
        #pragma unroll
        for (int jb = 0; jb < NJB; jb++) m = fmaxf(m, g_pm[jb][r]);
        float s = 0.f;
        #pragma unroll
        for (int jb = 0; jb < NJB; jb++) s += g_ps[jb][r] * expf(g_pm[jb][r] - m);
        s1 += m + logf(s);
        s0 += g_t0[r];
    }
    r0[t] = s0; r1[t] = s1; __syncthreads();
    for (int s = 128; s > 0; s >>= 1) {
        if (t < s) { r0[t] += r0[t + s]; r1[t] += r1[t + s]; }
        __syncthreads();
    }
    if (t == 0)
        out[0] = r0[0] / (float)NN - (r1[0] / (float)NN - logf((float)NN));
}

// ---------------------------------------------------------------------------
// Inputs: x_samples, y_samples, perm, W1, b1, W2, b2
// ---------------------------------------------------------------------------
extern "C" void kernel_launch(void* const* d_in, const int* in_sizes, int n_in,
                              void* d_out, int out_size) {
    const float* x    = (const float*)d_in[0];
    const float* y    = (const float*)d_in[1];
    const int*   perm = (const int*)d_in[2];
    const float* W1   = (const float*)d_in[3];
    const float* b1   = (const float*)d_in[4];
    const float* W2   = (const float*)d_in[5];
    const float* b2   = (const float*)d_in[6];
    float* out = (float*)d_out;

    dim3 blk(16, 16);
    dim3 ggrid(NN / 64, (HID + 63) / 64, 2);   // 120 CTAs
    gemm_hT<<<ggrid, blk>>>(x, y, W1);

    mid_kernel<<<300, 256>>>(perm, b1, W2, b2);

    pair_kernel<<<dim3(NN / 64, NN / 64), dim3(256, 2)>>>(b2);

    final_kernel<<<1, 256>>>(out);
}

// round 6
// speedup vs baseline: 1.0257x; 1.0257x over previous
#include <cuda_runtime.h>
#include <cuda_bf16.h>
#include <math.h>

#define NN 768
#define XD 768
#define HID 300
#define HP 304
#define W1COLS 1536
#define NJB 12

typedef unsigned long long ull;

// Scratch (device globals -- no allocation allowed)
__device__ float g_hxT[HP * NN];   // [h][n] hx^T ("c" side), rows >=300 zeroed
__device__ float g_hyT[HP * NN];   // [h][n] hy^T
__device__ float g_aT[HP * NN];    // [h][i] a = hy[perm i][h] + b1[h], pad rows zero
__device__ float g_w2p[HP];        // w2, 0 for h>=HID
__device__ float g_Ai[NN];
__device__ float g_Cj[NN];
__device__ float g_t0[NN];
__device__ float g_pm[NJB][NN];    // per (jblock,row) partial max
__device__ float g_ps[NJB][NN];    // per (jblock,row) partial sumexp
__device__ float g_lse[NN];

__device__ __forceinline__ ull add_f32x2(ull a, ull b) {
    ull d; asm("add.rn.f32x2 %0, %1, %2;" : "=l"(d) : "l"(a), "l"(b)); return d;
}
__device__ __forceinline__ ull fma_f32x2(ull a, ull b, ull c) {
    ull d; asm("fma.rn.f32x2 %0, %1, %2, %3;" : "=l"(d) : "l"(a), "l"(b), "l"(c)); return d;
}
__device__ __forceinline__ ull dup_f32(float f) {
    ull d; unsigned u = __float_as_uint(f);
    asm("mov.b64 %0, {%1, %2};" : "=l"(d) : "r"(u), "r"(u)); return d;
}
__device__ __forceinline__ float lo_f(ull v) { return __uint_as_float((unsigned)(v & 0xffffffffu)); }
__device__ __forceinline__ float hi_f(ull v) { return __uint_as_float((unsigned)(v >> 32)); }
__device__ __forceinline__ float softplus_f(float z) {
    return fmaxf(z, 0.f) + log1pf(expf(-fabsf(z)));
}
__device__ __forceinline__ void cp16(unsigned s, const void* g) {
    asm volatile("cp.async.ca.shared.global [%0], [%1], 16;" :: "r"(s), "l"(g) : "memory");
}
__device__ __forceinline__ void cp_commit() {
    asm volatile("cp.async.commit_group;" ::: "memory");
}
template<int N> __device__ __forceinline__ void cp_wait() {
    asm volatile("cp.async.wait_group %0;" :: "n"(N) : "memory");
}

// ---------------------------------------------------------------------------
// GEMM (packed f32x2), unchanged from R5.
// ---------------------------------------------------------------------------
__global__ void gemm_hT(const float* __restrict__ x, const float* __restrict__ y,
                        const float* __restrict__ W1) {
    __shared__ float sS[32][68];
    __shared__ ull   sWd[32][66];

    const int which = blockIdx.z;
    const float* S = which ? y : x;
    const int wofs = which ? XD : 0;
    float* outT = which ? g_hyT : g_hxT;

    const int n0 = blockIdx.x * 64;
    const int h0 = blockIdx.y * 64;
    const int tx = threadIdx.x, ty = threadIdx.y;
    const int tid = ty * 16 + tx;
    const int lr = tid >> 3;
    const int lc = (tid & 7) * 4;

    ull acc2[4][2] = {};

    for (int k0 = 0; k0 < XD; k0 += 32) {
        {
            float4 v0 = *(const float4*)&S[(size_t)(n0 + lr) * XD + k0 + lc];
            float4 v1 = *(const float4*)&S[(size_t)(n0 + lr + 32) * XD + k0 + lc];
            sS[lc + 0][lr] = v0.x; sS[lc + 1][lr] = v0.y;
            sS[lc + 2][lr] = v0.z; sS[lc + 3][lr] = v0.w;
            sS[lc + 0][lr + 32] = v1.x; sS[lc + 1][lr + 32] = v1.y;
            sS[lc + 2][lr + 32] = v1.z; sS[lc + 3][lr + 32] = v1.w;
        }
        {
            const int h1 = h0 + lr, h2 = h0 + lr + 32;
            float4 v0 = make_float4(0.f, 0.f, 0.f, 0.f), v1 = v0;
            if (h1 < HID) v0 = *(const float4*)&W1[(size_t)h1 * W1COLS + wofs + k0 + lc];
            if (h2 < HID) v1 = *(const float4*)&W1[(size_t)h2 * W1COLS + wofs + k0 + lc];
            sWd[lc + 0][lr] = dup_f32(v0.x); sWd[lc + 1][lr] = dup_f32(v0.y);
            sWd[lc + 2][lr] = dup_f32(v0.z); sWd[lc + 3][lr] = dup_f32(v0.w);
            sWd[lc + 0][lr + 32] = dup_f32(v1.x); sWd[lc + 1][lr + 32] = dup_f32(v1.y);
            sWd[lc + 2][lr + 32] = dup_f32(v1.z); sWd[lc + 3][lr + 32] = dup_f32(v1.w);
        }
        __syncthreads();

        #pragma unroll
        for (int kk = 0; kk < 32; kk++) {
            ulonglong2 wa = *(const ulonglong2*)&sWd[kk][ty * 4];
            ulonglong2 wb = *(const ulonglong2*)&sWd[kk][ty * 4 + 2];
            ulonglong2 bp = *(const ulonglong2*)&sS[kk][tx * 4];
            ull wd[4] = {wa.x, wa.y, wb.x, wb.y};
            #pragma unroll
            for (int p = 0; p < 4; p++) {
                acc2[p][0] = fma_f32x2(wd[p], bp.x, acc2[p][0]);
                acc2[p][1] = fma_f32x2(wd[p], bp.y, acc2[p][1]);
            }
        }
        __syncthreads();
    }

    #pragma unroll
    for (int p = 0; p < 4; p++) {
        const int h = h0 + ty * 4 + p;
        if (h < HID) {
            float4 v = make_float4(lo_f(acc2[p][0]), hi_f(acc2[p][0]),
                                   lo_f(acc2[p][1]), hi_f(acc2[p][1]));
            *(float4*)&outT[(size_t)h * NN + n0 + tx * 4] = v;
        }
    }
}

// ---------------------------------------------------------------------------
// mid_kernel (unchanged from R5)
// ---------------------------------------------------------------------------
__global__ void mid_kernel(const int* __restrict__ perm,
                           const float* __restrict__ b1,
                           const float* __restrict__ W2,
                           const float* __restrict__ b2) {
    __shared__ float red[8][33];
    const int b = blockIdx.x;
    const int t = threadIdx.x;

    if (b < 228) {
        const int idx4 = b * 256 + t;
        const int h = idx4 / (NN / 4);
        const int i = (idx4 - h * (NN / 4)) * 4;
        float4 v = make_float4(0.f, 0.f, 0.f, 0.f);
        if (h < HID) {
            const int4 pi = *(const int4*)&perm[i];
            const float* row = &g_hyT[(size_t)h * NN];
            const float bh = b1[h];
            v.x = row[pi.x] + bh; v.y = row[pi.y] + bh;
            v.z = row[pi.z] + bh; v.w = row[pi.w] + bh;
        } else {
            *(float4*)&g_hxT[(size_t)h * NN + i] = v;
        }
        *(float4*)&g_aT[(size_t)h * NN + i] = v;
        if (idx4 < HP) g_w2p[idx4] = (idx4 < HID) ? W2[idx4] : 0.f;
        return;
    }

    const int bs = b - 228;
    const int mode = bs / 24;
    const int tx = t & 31, ty = t >> 5;
    const int n = (bs % 24) * 32 + tx;

    float p = 0.f;
    if (mode == 0) {
        for (int h = ty; h < HID; h += 8) {
            float v = g_hxT[(size_t)h * NN + n] + g_hyT[(size_t)h * NN + n] + b1[h];
            p = fmaf(W2[h], fmaxf(v, 0.f), p);
        }
    } else if (mode == 1) {
        const int pi = perm[n];
        for (int h = ty; h < HID; h += 8)
            p = fmaf(W2[h], g_hyT[(size_t)h * NN + pi] + b1[h], p);
    } else {
        for (int h = ty; h < HID; h += 8)
            p = fmaf(W2[h], g_hxT[(size_t)h * NN + n], p);
    }
    red[ty][tx] = p;
    __syncthreads();
    if (ty == 0) {
        float s = red[0][tx];
        #pragma unroll
        for (int k = 1; k < 8; k++) s += red[k][tx];
        if (mode == 0)      g_t0[n] = softplus_f(s + b2[0]);
        else if (mode == 1) g_Ai[n] = s;
        else                g_Cj[n] = s;
    }
}

// ---------------------------------------------------------------------------
// Pair v5: 512 thr, 2-way h-split, cp.async DOUBLE-BUFFERED chunk pipeline.
// Packed f32x2 i-pair math. Fused per-(row, jblock) LSE partials.
// ---------------------------------------------------------------------------
__global__ void __launch_bounds__(512, 1) pair_kernel(const float* __restrict__ b2) {
    __shared__ float sA[2][2][16][64];   // [group][buf][h][i]
    __shared__ float sC[2][2][16][64];   // [group][buf][h][j]
    __shared__ float sw[HP];
    __shared__ ull   cbuf[256][8];

    const int g  = threadIdx.y;
    const int t  = threadIdx.x;
    const int tx = t & 15;
    const int ty = t >> 4;
    const int i0 = blockIdx.y * 64;
    const int j0 = blockIdx.x * 64;
    const int row = t >> 4;              // loader row 0..15
    const int col = (t & 15) * 4;        // loader col

    // stage w2 once
    if (g == 0) for (int h = t; h < HP; h += 256) sw[h] = g_w2p[h];

    const int c0 = g ? 10 : 0;
    const int c1 = g ? 19 : 10;          // 19 chunks (HP=304)

    // prefetch first chunk into buf 0
    {
        const int h0 = c0 * 16;
        cp16((unsigned)__cvta_generic_to_shared(&sA[g][0][row][col]),
             &g_aT[(size_t)(h0 + row) * NN + i0 + col]);
        cp16((unsigned)__cvta_generic_to_shared(&sC[g][0][row][col]),
             &g_hxT[(size_t)(h0 + row) * NN + j0 + col]);
        cp_commit();
    }
    __syncthreads();   // sw visible to both groups

    ull acc[2][4] = {};   // [i-pair][j]

    for (int ch = c0; ch < c1; ch++) {
        const int buf = (ch - c0) & 1;
        if (ch + 1 < c1) {
            const int h1 = (ch + 1) * 16;
            cp16((unsigned)__cvta_generic_to_shared(&sA[g][buf ^ 1][row][col]),
                 &g_aT[(size_t)(h1 + row) * NN + i0 + col]);
            cp16((unsigned)__cvta_generic_to_shared(&sC[g][buf ^ 1][row][col]),
                 &g_hxT[(size_t)(h1 + row) * NN + j0 + col]);
            cp_commit();
            cp_wait<1>();
        } else {
            cp_wait<0>();
        }
        asm volatile("bar.sync %0, 256;" :: "r"(g + 1) : "memory");

        const int h0 = ch * 16;
        #pragma unroll
        for (int hh = 0; hh < 16; hh++) {
            const ull wv = dup_f32(sw[h0 + hh]);
            ulonglong2 pa = *(const ulonglong2*)&sA[g][buf][hh][ty * 4];
            float4 c4 = *(const float4*)&sC[g][buf][hh][tx * 4];
            ull pa2[2] = {pa.x, pa.y};
            ull cd[4] = {dup_f32(c4.x), dup_f32(c4.y), dup_f32(c4.z), dup_f32(c4.w)};
            #pragma unroll
            for (int p2 = 0; p2 < 2; p2++) {
                #pragma unroll
                for (int q = 0; q < 4; q++) {
                    ull v = add_f32x2(pa2[p2], cd[q]);
                    v &= 0x7FFFFFFF7FFFFFFFULL;
                    acc[p2][q] = fma_f32x2(wv, v, acc[p2][q]);
                }
            }
        }
        asm volatile("bar.sync %0, 256;" :: "r"(g + 1) : "memory");
    }

    // combine subgroup partials
    if (g == 1) {
        #pragma unroll
        for (int p2 = 0; p2 < 2; p2++)
            #pragma unroll
            for (int q = 0; q < 4; q++)
                cbuf[t][p2 * 4 + q] = acc[p2][q];
    }
    __syncthreads();
    if (g == 0) {
        const float bb = b2[0];
        float cj[4], ai[4];
        *(float4*)cj = *(const float4*)&g_Cj[j0 + tx * 4];
        *(float4*)ai = *(const float4*)&g_Ai[i0 + ty * 4];

        #pragma unroll
        for (int p2 = 0; p2 < 2; p2++) {
            acc[p2][0] = add_f32x2(acc[p2][0], cbuf[t][p2 * 4 + 0]);
            acc[p2][1] = add_f32x2(acc[p2][1], cbuf[t][p2 * 4 + 1]);
            acc[p2][2] = add_f32x2(acc[p2][2], cbuf[t][p2 * 4 + 2]);
            acc[p2][3] = add_f32x2(acc[p2][3], cbuf[t][p2 * 4 + 3]);

            float vlo[4], vhi[4];
            #pragma unroll
            for (int q = 0; q < 4; q++) {
                vlo[q] = softplus_f(fmaf(0.5f, lo_f(acc[p2][q]) + ai[2*p2]     + cj[q], bb));
                vhi[q] = softplus_f(fmaf(0.5f, hi_f(acc[p2][q]) + ai[2*p2 + 1] + cj[q], bb));
            }
            // per-row LSE partials over this 64-j block (16 lanes per row)
            float mlo = fmaxf(fmaxf(vlo[0], vlo[1]), fmaxf(vlo[2], vlo[3]));
            float mhi = fmaxf(fmaxf(vhi[0], vhi[1]), fmaxf(vhi[2], vhi[3]));
            #pragma unroll
            for (int o = 1; o < 16; o <<= 1) {
                mlo = fmaxf(mlo, __shfl_xor_sync(0xffffffffu, mlo, o));
                mhi = fmaxf(mhi, __shfl_xor_sync(0xffffffffu, mhi, o));
            }
            float slo = expf(vlo[0]-mlo) + expf(vlo[1]-mlo) + expf(vlo[2]-mlo) + expf(vlo[3]-mlo);
            float shi = expf(vhi[0]-mhi) + expf(vhi[1]-mhi) + expf(vhi[2]-mhi) + expf(vhi[3]-mhi);
            #pragma unroll
            for (int o = 1; o < 16; o <<= 1) {
                slo += __shfl_xor_sync(0xffffffffu, slo, o);
                shi += __shfl_xor_sync(0xffffffffu, shi, o);
            }
            if (tx == 0) {
                g_pm[blockIdx.x][i0 + ty * 4 + 2*p2]     = mlo;
                g_ps[blockIdx.x][i0 + ty * 4 + 2*p2]     = slo;
                g_pm[blockIdx.x][i0 + ty * 4 + 2*p2 + 1] = mhi;
                g_ps[blockIdx.x][i0 + ty * 4 + 2*p2 + 1] = shi;
            }
        }
    }
}

// ---------------------------------------------------------------------------
// Parallel LSE merge (one row per thread), then tiny final reduce.
// ---------------------------------------------------------------------------
__global__ void lse_merge_kernel() {
    const int r = blockIdx.x * 128 + threadIdx.x;
    if (r >= NN) return;
    float m = -INFINITY;
    #pragma unroll
    for (int jb = 0; jb < NJB; jb++) m = fmaxf(m, g_pm[jb][r]);
    float s = 0.f;
    #pragma unroll
    for (int jb = 0; jb < NJB; jb++) s += g_ps[jb][r] * expf(g_pm[jb][r] - m);
    g_lse[r] = m + logf(s);
}

__global__ void final_kernel(float* __restrict__ out) {
    __shared__ float r0[256], r1[256];
    const int t = threadIdx.x;
    float s0 = 0.f, s1 = 0.f;
    for (int r = t; r < NN; r += 256) { s0 += g_t0[r]; s1 += g_lse[r]; }
    r0[t] = s0; r1[t] = s1; __syncthreads();
    for (int s = 128; s > 0; s >>= 1) {
        if (t < s) { r0[t] += r0[t + s]; r1[t] += r1[t + s]; }
        __syncthreads();
    }
    if (t == 0)
        out[0] = r0[0] / (float)NN - (r1[0] / (float)NN - logf((float)NN));
}

// ---------------------------------------------------------------------------
// Inputs: x_samples, y_samples, perm, W1, b1, W2, b2
// ---------------------------------------------------------------------------
extern "C" void kernel_launch(void* const* d_in, const int* in_sizes, int n_in,
                              void* d_out, int out_size) {
    const float* x    = (const float*)d_in[0];
    const float* y    = (const float*)d_in[1];
    const int*   perm = (const int*)d_in[2];
    const float* W1   = (const float*)d_in[3];
    const float* b1   = (const float*)d_in[4];
    const float* W2   = (const float*)d_in[5];
    const float* b2   = (const float*)d_in[6];
    float* out = (float*)d_out;

    dim3 blk(16, 16);
    dim3 ggrid(NN / 64, (HID + 63) / 64, 2);
    gemm_hT<<<ggrid, blk>>>(x, y, W1);

    mid_kernel<<<300, 256>>>(perm, b1, W2, b2);

    pair_kernel<<<dim3(NN / 64, NN / 64), dim3(256, 2)>>>(b2);

    lse_merge_kernel<<<6, 128>>>();
    final_kernel<<<1, 256>>>(out);
}